// round 17
// baseline (speedup 1.0000x reference)
#include <cuda_runtime.h>

// Problem constants
#define NV    32
#define DM    256
#define MM    128
#define DN    64
#define NL    3
#define BATCH 512
#define RPB   4                    // batch rows per block
#define NBLK  (BATCH / RPB)        // 128 blocks
#define NT    512                  // threads per block
#define AROW  260                  // splat activation row stride (ull), even
#define PCROW 130                  // pc buffer row stride (ull, K-pair format)

// Scratch (device global: no allocations allowed)
__device__ float g_noise[BATCH * NV * DM];       // 16 MB: gelu(nz @ ne_W + ne_b)

typedef unsigned long long ull;

// ---- packed f32x2 helpers ----
__device__ __forceinline__ ull pack2(float w) {
    ull r; asm("mov.b64 %0, {%1, %1};" : "=l"(r) : "f"(w)); return r;
}
__device__ __forceinline__ ull pack2f(float a, float b) {
    ull r; asm("mov.b64 %0, {%1, %2};" : "=l"(r) : "f"(a), "f"(b)); return r;
}
__device__ __forceinline__ void ffma2(ull &acc, ull x, ull w) {
    asm("fma.rn.f32x2 %0, %1, %2, %3;" : "=l"(acc) : "l"(x), "l"(w), "l"(acc));
}
__device__ __forceinline__ ull fadd2(ull a, ull b) {
    ull r; asm("add.rn.f32x2 %0, %1, %2;" : "=l"(r) : "l"(a), "l"(b)); return r;
}
__device__ __forceinline__ float2 asf2(ull a) {
    float2 f; asm("mov.b64 {%0, %1}, %2;" : "=f"(f.x), "=f"(f.y) : "l"(a)); return f;
}
__device__ __forceinline__ float gelu(float x) {
    return 0.5f * x * (1.0f + erff(x * 0.7071067811865476f));   // exact erf GELU
}

// ============================================================================
// Kernel: noise encoder precompute (v2).
// grid (8 rowgroups, 32 vars), 256 threads. Each block: 64 rows in two
// 32-row groups; the second group's neW reads hit L1 (64KB, smem only 8KB).
// ============================================================================
__global__ void __launch_bounds__(256, 4) noise_kernel(
    const float* __restrict__ nz,    // (B, NV, DN)
    const float* __restrict__ neW,   // (NV, DN, DM)
    const float* __restrict__ neb)   // (NV, DM)
{
    const int i  = blockIdx.y;
    const int rg = blockIdx.x;
    const int d  = threadIdx.x;

    __shared__ __align__(16) ull s_nzp[DN][16];

    const float* __restrict__ W = neW + i * DN * DM + d;
    const float bias = neb[i * DM + d];

    for (int g = 0; g < 2; g++) {
        const int b0 = (rg * 2 + g) * 32;
        __syncthreads();                      // protect s_nzp reuse across groups
        for (int idx = d; idx < DN * 16; idx += 256) {
            int k = idx >> 4, rp = idx & 15;
            int b = b0 + rp * 2;
            s_nzp[k][rp] = pack2f(nz[(b * NV + i) * DN + k],
                                  nz[((b + 1) * NV + i) * DN + k]);
        }
        __syncthreads();

        ull acc[16];
        #pragma unroll
        for (int rp = 0; rp < 16; rp++) acc[rp] = 0;

        #pragma unroll 2
        for (int k = 0; k < DN; k++) {
            ull w2 = pack2(__ldg(W + k * DM));
            const ulonglong2* row = reinterpret_cast<const ulonglong2*>(s_nzp[k]);
            #pragma unroll
            for (int j = 0; j < 8; j++) {
                ulonglong2 x = row[j];
                ffma2(acc[2 * j],     x.x, w2);
                ffma2(acc[2 * j + 1], x.y, w2);
            }
        }
        #pragma unroll
        for (int rp = 0; rp < 16; rp++) {
            float2 f = asf2(acc[rp]);
            int b = b0 + rp * 2;
            g_noise[((long long)b * NV + i) * DM + d]       = gelu(f.x + bias);
            g_noise[((long long)(b + 1) * NV + i) * DM + d] = gelu(f.y + bias);
        }
    }
}

// ============================================================================
// Split-K partial GEMM, column-pair lanes (R16, proven). Thread = (cg, ks):
// 4 cols x 4 rows. Acts: adjacent dim-splats via one LDS.128 broadcast.
// Weights: LDG.128 per k, consumed directly as two aligned f32x2 operands.
// ============================================================================
struct WPre { ulonglong2 w0, w1; };   // k=0 and k=1 weights for this thread

template<int N, int K>
__device__ __forceinline__ WPre wpref(const float* __restrict__ W, int t)
{
    constexpr int CG = N / 4;
    constexpr int KS = NT / CG;
    constexpr int KC = K / KS;
    const int cg = t & (CG - 1);
    const int ks = t / CG;
    const int j0 = cg * 4;
    const ulonglong2* __restrict__ base =
        reinterpret_cast<const ulonglong2*>(W + (size_t)(ks * KC) * N + j0);
    WPre p;
    p.w0 = __ldg(base);
    p.w1 = __ldg(base + N / 4);
    return p;
}

template<int N, int K>
__device__ __forceinline__ void split_partial(
    const ull* __restrict__ sinu, float* __restrict__ red,
    const float* __restrict__ W, int t, WPre pre)
{
    constexpr int CG = N / 4;
    constexpr int KS = NT / CG;
    constexpr int KC = K / KS;
    const int cg = t & (CG - 1);
    const int ks = t / CG;
    const int j0 = cg * 4;

    ull acc[2][4];                       // [colpair][row]
    #pragma unroll
    for (int c = 0; c < 2; c++)
        #pragma unroll
        for (int r = 0; r < 4; r++) acc[c][r] = 0;

    const ulonglong2* __restrict__ wq =
        reinterpret_cast<const ulonglong2*>(W + (size_t)(ks * KC) * N + j0);
    const ull* __restrict__ x = sinu + ks * KC;

    #pragma unroll
    for (int d = 0; d < KC; d += 2) {
        ulonglong2 wv0 = (d == 0) ? pre.w0 : __ldg(wq + d * (N / 4));
        ulonglong2 wv1 = (d == 0) ? pre.w1 : __ldg(wq + (d + 1) * (N / 4));
        #pragma unroll
        for (int r = 0; r < 4; r++) {
            ulonglong2 xv = *reinterpret_cast<const ulonglong2*>(x + r * AROW + d);
            ffma2(acc[0][r], xv.x, wv0.x);
            ffma2(acc[1][r], xv.x, wv0.y);
            ffma2(acc[0][r], xv.y, wv1.x);
            ffma2(acc[1][r], xv.y, wv1.y);
        }
    }
    #pragma unroll
    for (int r = 0; r < 4; r++)
        *reinterpret_cast<ulonglong2*>(red + (r * KS + ks) * N + j0) =
            make_ulonglong2(acc[0][r], acc[1][r]);
}

// ---- reduce partials (tree) -> gelu -> splat activation rows ----
template<int N>
__device__ __forceinline__ void reduce_act(
    const float* __restrict__ red, ull* __restrict__ soutu,
    const float* __restrict__ bias, int t)
{
    constexpr int KS = 2048 / N;
    constexpr int J2 = N / 2;
    const int j2 = t & (J2 - 1);
    const int r  = (N == 256) ? (t >> 7) : (t >> 6);
    const ull* __restrict__ rp = reinterpret_cast<const ull*>(red);
    ull v[KS];
    #pragma unroll
    for (int k = 0; k < KS; k++)
        v[k] = rp[(r * KS + k) * (N / 2) + j2];
    #pragma unroll
    for (int stride = KS / 2; stride > 0; stride >>= 1)
        #pragma unroll
        for (int k = 0; k < stride; k++)
            v[k] = fadd2(v[k], v[k + stride]);
    const float2 bb = __ldg(reinterpret_cast<const float2*>(bias) + j2);
    ull s = fadd2(v[0], pack2f(bb.x, bb.y));
    float2 f = asf2(s);
    *reinterpret_cast<ulonglong2*>(soutu + r * AROW + 2 * j2) =
        make_ulonglong2(pack2(gelu(f.x)), pack2(gelu(f.y)));
}

// ---- pc partial for NEXT target (K-pair format, on idle upper threads) ----
__device__ __forceinline__ void pc_part(
    int half, int i, int tgt, int vmax,
    const float* __restrict__ s_val, const ull* __restrict__ s_adj2,
    const float* __restrict__ var_emb, ull* __restrict__ s_pc, int tu)
{
    const int id = half * 256 + tu;
    const int r  = id >> 7;
    const int j2 = id & 127;
    const float2 e = __ldg(reinterpret_cast<const float2*>(var_emb + tgt * DM) + j2);
    ull acc = pack2f(e.x, e.y);
    const float* vp = s_val + r * DM + j2 * 2;
    const ull* arow = s_adj2 + tgt * NV;
    #pragma unroll 4
    for (int v = 0; v < vmax; v++) {
        if (v == i) continue;                         // current var fused later
        ull x = *reinterpret_cast<const ull*>(vp + v * (4 * DM));
        ffma2(acc, x, arow[v]);
    }
    s_pc[r * PCROW + j2] = acc;
}

// ============================================================================
// Main kernel (R16, proven)
// ============================================================================
__global__ void __launch_bounds__(NT, 1) scm_kernel(
    const float* __restrict__ edge_logits,
    const float* __restrict__ var_emb,
    const float* __restrict__ paW,
    const float* __restrict__ pab,
    const float* __restrict__ mW1,
    const float* __restrict__ mb1,
    const float* __restrict__ mW2,
    const float* __restrict__ mb2,
    const float* __restrict__ mW3,
    const float* __restrict__ mb3,
    float* __restrict__ out)
{
    extern __shared__ __align__(16) ull smem[];
    float* s_red  = reinterpret_cast<float*>(smem);          // 4096 ull = 32KB
    ull*   s_a    = smem + 4096;                             // 1040 ull (4 x AROW)
    ull*   s_b    = smem + 5136;                             // 1040 ull
    ull*   s_pc   = smem + 6176;                             // 520 ull
    ull*   s_adj2 = smem + 6696;                             // 1024 ull
    float* s_val  = reinterpret_cast<float*>(smem + 7720);   // 32768 fl = 128KB

    const int t = threadIdx.x;
    const int row0 = blockIdx.x * RPB;
    const int j2f = t & 127;
    const int rf  = t >> 7;

    // adjacency: sigmoid((logits * offdiag)/0.5); diagonal -> 0.5 (splat ull)
    for (int idx = t; idx < NV * NV; idx += NT) {
        int ii = idx / NV, v = idx % NV;
        float z = (v == ii) ? 0.0f : edge_logits[v * NV + ii] * 2.0f;
        s_adj2[idx] = pack2(1.0f / (1.0f + expf(-z)));
    }
    // step 0 input: s_a = splat(emb[0])
    {
        const float2 e = __ldg(reinterpret_cast<const float2*>(var_emb) + j2f);
        *reinterpret_cast<ulonglong2*>(s_a + rf * AROW + 2 * j2f) =
            make_ulonglong2(pack2(e.x), pack2(e.y));
    }
    WPre pre_pa = wpref<DM, DM>(paW, t);
    __syncthreads();

    for (int s = 0; s < NL * NV; s++) {
        const int i = s & 31;
        const bool last = (s >= 2 * NV);
        const bool has_tgt = (s < NL * NV - 1);
        const int tgt = (i + 1) & 31;
        const int vmax = (s + 1 < NV) ? i : NV;

        // ---- pa: parent_input partials ; prefetch w1
        split_partial<DM, DM>(s_a, s_red, paW, t, pre_pa);
        WPre pre_w1 = wpref<MM, DM>(mW1 + i * (DM * MM), t);
        __syncthreads();

        reduce_act<DM>(s_red, s_b, pab, t);
        __syncthreads();

        // ---- w1: 256 -> 128 ; prefetch w2
        split_partial<MM, DM>(s_b, s_red, mW1 + i * (DM * MM), t, pre_w1);
        WPre pre_w2 = wpref<MM, MM>(mW2 + i * (MM * MM), t);
        __syncthreads();

        if (t < 256) reduce_act<MM>(s_red, s_a, mb1 + i * MM, t);
        else if (has_tgt) pc_part(0, i, tgt, vmax, s_val, s_adj2, var_emb, s_pc, t & 255);
        __syncthreads();

        // ---- w2: 128 -> 128 ; prefetch w3
        split_partial<MM, MM>(s_a, s_red, mW2 + i * (MM * MM), t, pre_w2);
        WPre pre_w3 = wpref<DM, MM>(mW3 + i * (MM * DM), t);
        __syncthreads();

        if (t < 256) reduce_act<MM>(s_red, s_b, mb2 + i * MM, t);
        else if (has_tgt) pc_part(1, i, tgt, vmax, s_val, s_adj2, var_emb, s_pc, t & 255);
        __syncthreads();

        // ---- w3: 128 -> 256 (partials) ; prefetch pa for next step
        split_partial<DM, MM>(s_b, s_red, mW3 + i * (MM * DM), t, pre_w3);
        pre_pa = wpref<DM, DM>(paW, t);
        __syncthreads();

        // ---- final: sum partials (tree) + bias + noise -> s_val, out (last),
        //      fuse pc and write next step's splat input
        {
            const ull* rp = reinterpret_cast<const ull*>(s_red);
            ull v[8];
            #pragma unroll
            for (int k = 0; k < 8; k++)
                v[k] = rp[(rf * 8 + k) * 128 + j2f];
            #pragma unroll
            for (int stride = 4; stride > 0; stride >>= 1)
                #pragma unroll
                for (int k = 0; k < stride; k++)
                    v[k] = fadd2(v[k], v[k + stride]);
            const float2 b2 = __ldg(reinterpret_cast<const float2*>(mb3 + i * DM) + j2f);
            long long gidx = ((long long)(row0 + rf) * NV + i) * DM + j2f * 2;
            const float2 n2 = __ldg(reinterpret_cast<const float2*>(g_noise + gidx));
            float2 f = asf2(v[0]);
            float2 v2 = make_float2(f.x + b2.x + n2.x, f.y + b2.y + n2.y);
            *reinterpret_cast<float2*>(s_val + (i * 4 + rf) * DM + j2f * 2) = v2;
            if (last) *reinterpret_cast<float2*>(out + gidx) = v2;
            if (has_tgt) {
                ull pcv = s_pc[rf * PCROW + j2f];
                ffma2(pcv, pack2f(v2.x, v2.y), s_adj2[tgt * NV + i]);
                float2 pf = asf2(pcv);
                *reinterpret_cast<ulonglong2*>(s_a + rf * AROW + 2 * j2f) =
                    make_ulonglong2(pack2(pf.x), pack2(pf.y));
            }
        }
        __syncthreads();
    }
}

// ============================================================================
// Launch
// ============================================================================
#define SCM_SMEM ((7720 + 16384) * 8)   // 192832 bytes

extern "C" void kernel_launch(void* const* d_in, const int* in_sizes, int n_in,
                              void* d_out, int out_size)
{
    const float* nz   = (const float*)d_in[0];
    const float* elog = (const float*)d_in[1];
    const float* emb  = (const float*)d_in[2];
    const float* paW  = (const float*)d_in[3];
    const float* pab  = (const float*)d_in[4];
    const float* mW1  = (const float*)d_in[5];
    const float* mb1  = (const float*)d_in[6];
    const float* mW2  = (const float*)d_in[7];
    const float* mb2  = (const float*)d_in[8];
    const float* mW3  = (const float*)d_in[9];
    const float* mb3  = (const float*)d_in[10];
    const float* neW  = (const float*)d_in[11];
    const float* neb  = (const float*)d_in[12];
    float* out = (float*)d_out;

    cudaFuncSetAttribute(scm_kernel, cudaFuncAttributeMaxDynamicSharedMemorySize, SCM_SMEM);

    noise_kernel<<<dim3(8, NV), 256>>>(nz, neW, neb);
    scm_kernel<<<NBLK, NT, SCM_SMEM>>>(elog, emb, paW, pab,
                                       mW1, mb1, mW2, mb2, mW3, mb3, out);
}